// round 15
// baseline (speedup 1.0000x reference)
#include <cuda_runtime.h>
#include <cuda_bf16.h>
#include <mma.h>
#include <cstdint>

using namespace nvcuda;

// Problem dims (fixed)
#define BATCH 8
#define TLEN  4096
#define IDIM  1024
#define NDIM  64
#define BT    (BATCH * TLEN)      // 32768
#define CH    64                  // scan chunk length (= K1 M tile)
#define NCH   (TLEN / CH)         // 64 chunks per batch

// ---------------------------------------------------------------------------
// Scratch (device globals; allocation forbidden)
// ---------------------------------------------------------------------------
__device__ __nv_bfloat16 g_Bb[NDIM * IDIM];      // Bbar bf16 [n][k]
__device__ __nv_bfloat16 g_Cb[IDIM * NDIM];      // C bf16 [i][n]
__device__ float g_a[NDIM];                      // A_bar_state
__device__ float g_Bu[(size_t)BT * NDIM];        // locally-scanned x (8 MB)
__device__ float g_end[BATCH * NCH * NDIM];      // chunk-local end states
__device__ float g_carry[BATCH * NCH * NDIM];    // carry-in per chunk
__device__ float g_apow[CH * NDIM];              // a_n^(t+1), t=0..63

// ---------------------------------------------------------------------------
// K0: per-n Bbar = B*softplus(logdelta) -> bf16; a_n = mean_i exp(d_i A_n)
// (C conversion moved into k_gemm1's grid)
// ---------------------------------------------------------------------------
__global__ void k_setup(const float* __restrict__ logA,
                        const float* __restrict__ B,
                        const float* __restrict__ logdelta) {
    int n = blockIdx.x;
    float A = -expf(logA[n]);
    __shared__ float red[256];
    float s = 0.f;
    for (int i = threadIdx.x; i < IDIM; i += 256) {
        float ld = logdelta[i];
        float d  = (ld > 20.f) ? ld : log1pf(expf(ld));
        g_Bb[n * IDIM + i] = __float2bfloat16_rn(B[n * IDIM + i] * d);
        s += expf(d * A);
    }
    red[threadIdx.x] = s;
    __syncthreads();
    for (int o = 128; o > 0; o >>= 1) {
        if (threadIdx.x < o) red[threadIdx.x] += red[threadIdx.x + o];
        __syncthreads();
    }
    if (threadIdx.x == 0) g_a[n] = red[0] * (1.f / IDIM);
}

// ---------------------------------------------------------------------------
// K1: wmma GEMM1 + in-smem local scan epilogue (R13 ping-pong, unchanged),
//     plus 64 trailing blocks (blockIdx >= 512) converting C -> bf16.
// ---------------------------------------------------------------------------
#define G1_LDA 72
#define G1_LDY 68
#define G1_AS   0                                 // 2 x 9216
#define G1_BS   (2 * 64 * G1_LDA * 2)             // 18432, 2 x 9216
#define G1_STG  (64 * G1_LDA * 2)                 // stage stride 9216
#define G1_YBU  0
#define G1_SEG  (64 * G1_LDY * 4)                 // 17408
#define G1_SMEM 36864

__global__ __launch_bounds__(256) void k_gemm1(const float* __restrict__ u,
                                               const float* __restrict__ C) {
    if (blockIdx.x >= BT / 64) {                  // C-convert blocks
        int idx = (blockIdx.x - BT / 64) * 256 + threadIdx.x;
        float4 v = *reinterpret_cast<const float4*>(C + 4 * (size_t)idx);
        __nv_bfloat162 lo = __floats2bfloat162_rn(v.x, v.y);
        __nv_bfloat162 hi = __floats2bfloat162_rn(v.z, v.w);
        uint2 pk = make_uint2(*reinterpret_cast<unsigned*>(&lo),
                              *reinterpret_cast<unsigned*>(&hi));
        *reinterpret_cast<uint2*>(&g_Cb[4 * (size_t)idx]) = pk;
        return;
    }
    extern __shared__ char smem[];
    float*        Ybu = reinterpret_cast<float*>(smem + G1_YBU);
    float*        seg = reinterpret_cast<float*>(smem + G1_SEG);

    const int tid = threadIdx.x;
    const int wid = tid >> 5;
    const int wy  = wid >> 2;                    // 0..1 -> m offset 32*wy
    const int wx  = wid & 3;                     // 0..3 -> n offset 16*wx
    const int m0  = blockIdx.x * 64;
    const float* ub = &u[(size_t)m0 * IDIM];

    wmma::fragment<wmma::accumulator, 16, 16, 16, float> acc[2];
#pragma unroll
    for (int a = 0; a < 2; a++) wmma::fill_fragment(acc[a], 0.f);

    float4 r[4];
    uint2  bb[4];
#pragma unroll
    for (int q = 0; q < 4; q++) {
        int idx = tid + 256 * q;
        int row = idx >> 4;
        int k   = (idx & 15) << 2;
        r[q]  = *reinterpret_cast<const float4*>(&ub[(size_t)row * IDIM + k]);
        bb[q] = *reinterpret_cast<const uint2*>(&g_Bb[row * IDIM + k]);
    }

    int buf = 0;
    for (int kc = 0; kc < IDIM; kc += 64) {
        __nv_bfloat16* As = reinterpret_cast<__nv_bfloat16*>(smem + G1_AS + buf * G1_STG);
        __nv_bfloat16* Bs = reinterpret_cast<__nv_bfloat16*>(smem + G1_BS + buf * G1_STG);
#pragma unroll
        for (int q = 0; q < 4; q++) {
            int idx = tid + 256 * q;
            int row = idx >> 4;
            int k   = (idx & 15) << 2;
            __nv_bfloat162 lo = __floats2bfloat162_rn(r[q].x, r[q].y);
            __nv_bfloat162 hi = __floats2bfloat162_rn(r[q].z, r[q].w);
            uint2 pk = make_uint2(*reinterpret_cast<unsigned*>(&lo),
                                  *reinterpret_cast<unsigned*>(&hi));
            *reinterpret_cast<uint2*>(&As[row * G1_LDA + k]) = pk;
            *reinterpret_cast<uint2*>(&Bs[row * G1_LDA + k]) = bb[q];
        }
        __syncthreads();

        if (kc + 64 < IDIM) {
#pragma unroll
            for (int q = 0; q < 4; q++) {
                int idx = tid + 256 * q;
                int row = idx >> 4;
                int k   = (idx & 15) << 2;
                r[q]  = *reinterpret_cast<const float4*>(
                    &ub[(size_t)row * IDIM + kc + 64 + k]);
                bb[q] = *reinterpret_cast<const uint2*>(
                    &g_Bb[row * IDIM + kc + 64 + k]);
            }
        }

#pragma unroll
        for (int ks = 0; ks < 4; ks++) {
            int k = ks * 16;
            wmma::fragment<wmma::matrix_a, 16, 16, 16, __nv_bfloat16, wmma::row_major> af[2];
            wmma::fragment<wmma::matrix_b, 16, 16, 16, __nv_bfloat16, wmma::col_major> bf;
#pragma unroll
            for (int mi = 0; mi < 2; mi++)
                wmma::load_matrix_sync(af[mi], &As[(wy * 32 + mi * 16) * G1_LDA + k], G1_LDA);
            wmma::load_matrix_sync(bf, &Bs[(wx * 16) * G1_LDA + k], G1_LDA);
#pragma unroll
            for (int mi = 0; mi < 2; mi++)
                wmma::mma_sync(acc[mi], af[mi], bf, acc[mi]);
        }
        buf ^= 1;
    }
    __syncthreads();

#pragma unroll
    for (int mi = 0; mi < 2; mi++)
        wmma::store_matrix_sync(&Ybu[(wy * 32 + mi * 16) * G1_LDY + wx * 16],
                                acc[mi], G1_LDY, wmma::mem_row_major);
    __syncthreads();

    const int n = tid & 63, q = tid >> 6;
    const float a = g_a[n];
    {
        float* p = &Ybu[(q * 16) * G1_LDY + n];
        float x = 0.f;
#pragma unroll
        for (int j = 0; j < 16; j++) {
            x = x * a + p[j * G1_LDY];
            p[j * G1_LDY] = x;
        }
        seg[q * 64 + n] = x;
    }
    __syncthreads();
    if (q > 0) {
        float a16 = a;
#pragma unroll
        for (int s = 0; s < 4; s++) a16 *= a16;   // a^16
        float S = seg[n];
        for (int pp = 1; pp < q; pp++) S = S * a16 + seg[pp * 64 + n];
        float f = S;
        float* p = &Ybu[(q * 16) * G1_LDY + n];
#pragma unroll
        for (int j = 0; j < 16; j++) {
            f *= a;
            p[j * G1_LDY] += f;
        }
    }
    __syncthreads();

#pragma unroll
    for (int qq = 0; qq < 4; qq++) {
        int idx = tid + 256 * qq;
        int row = idx >> 4;
        int c4  = (idx & 15) << 2;
        float4 v = *reinterpret_cast<const float4*>(&Ybu[row * G1_LDY + c4]);
        *reinterpret_cast<float4*>(&g_Bu[(size_t)(m0 + row) * NDIM + c4]) = v;
    }
    if (tid < 64) g_end[blockIdx.x * 64 + tid] = Ybu[63 * G1_LDY + tid];
}

// ---------------------------------------------------------------------------
// Kc: blocks 0..7 -> per-batch carry scan over 64 chunks; block 8 -> apow.
// ---------------------------------------------------------------------------
__global__ void k_carry() {
    int n = threadIdx.x;
    if (blockIdx.x < BATCH) {
        int b = blockIdx.x;
        float e[NCH];
#pragma unroll
        for (int c = 0; c < NCH; c++) e[c] = g_end[(b * NCH + c) * 64 + n];
        float a = g_a[n], aL = a;
#pragma unroll
        for (int s = 0; s < 6; s++) aL *= aL;     // a^64 = a^CH
        float carry = 0.f;
#pragma unroll
        for (int c = 0; c < NCH; c++) {
            g_carry[(b * NCH + c) * 64 + n] = carry;
            carry = carry * aL + e[c];
        }
    } else {
        float a = g_a[n], p = a;
        for (int j = 0; j < CH; j++) {
            g_apow[j * 64 + n] = p;               // a^(j+1)
            p *= a;
        }
    }
}

// ---------------------------------------------------------------------------
// K2: wmma GEMM2 (512 thr, 16 warps 4x4, warp 32x32) + full-u cp.async.
//   smem: [Xs 18432 | Cs 18432 | Ubuf 65536] = 102400. Ys(64 rows, 33792)
//   aliases dead Xs/Cs after MMA; epilogue runs in two row-halves.
//   All bulk global reads via cp.async.cg / __ldcg (L1 bypass).
// ---------------------------------------------------------------------------
#define G2_LDA 72
#define G2_LDY 132
#define G2_XS   0
#define G2_CS   18432
#define G2_YS   0
#define G2_U    36864
#define G2_SMEM (G2_U + 65536)                   // 102400

__global__ __launch_bounds__(512, 2) void k_gemm2(const float* __restrict__ u,
                                                  const float* __restrict__ D,
                                                  float* __restrict__ y) {
    extern __shared__ char smem[];
    __nv_bfloat16* Xs = reinterpret_cast<__nv_bfloat16*>(smem + G2_XS);
    __nv_bfloat16* Cs = reinterpret_cast<__nv_bfloat16*>(smem + G2_CS);
    float*         Ys = reinterpret_cast<float*>(smem + G2_YS);
    float*         Us = reinterpret_cast<float*>(smem + G2_U);

    const int tid = threadIdx.x;
    const int wid = tid >> 5;
    const int wy  = wid >> 2;                    // m offset 32*wy
    const int wx  = wid & 3;                     // i offset 32*wx
    const int m0  = blockIdx.x * 128;
    const int i0  = blockIdx.y * 128;
    const int chk2 = blockIdx.x * 2;

    // cp.async prefetch: full u tile 128 rows x 128 cols (4096 x 16B, 8/thread)
    {
        uint32_t ubase = (uint32_t)__cvta_generic_to_shared(smem + G2_U);
#pragma unroll
        for (int q = 0; q < 8; q++) {
            int idx = tid + 512 * q;             // 0..4095
            int row = idx >> 5;                  // 0..127
            int c16 = (idx & 31) * 16;
            const char* src = reinterpret_cast<const char*>(
                &u[(size_t)(m0 + row) * IDIM + i0]) + c16;
            asm volatile("cp.async.cg.shared.global [%0], [%1], 16;"
                         :: "r"(ubase + row * 512 + c16), "l"(src));
        }
        asm volatile("cp.async.commit_group;");
    }

    // xs tile: fixup + bf16 convert (4 float4/thread); g_Bu via .cg
#pragma unroll
    for (int q = 0; q < 4; q++) {
        int idx = tid + 512 * q;
        int row = idx >> 4;                      // 0..127
        int c4  = (idx & 15) << 2;
        float4 bu = __ldcg(reinterpret_cast<const float4*>(
            &g_Bu[(size_t)(m0 + row) * NDIM + c4]));
        float4 ap = *reinterpret_cast<const float4*>(&g_apow[(row & 63) * 64 + c4]);
        float4 cr = *reinterpret_cast<const float4*>(
            &g_carry[(chk2 + (row >> 6)) * 64 + c4]);
        float x0 = bu.x + cr.x * ap.x;
        float x1 = bu.y + cr.y * ap.y;
        float x2 = bu.z + cr.z * ap.z;
        float x3 = bu.w + cr.w * ap.w;
        __nv_bfloat162 lo = __floats2bfloat162_rn(x0, x1);
        __nv_bfloat162 hi = __floats2bfloat162_rn(x2, x3);
        uint2 pk = make_uint2(*reinterpret_cast<unsigned*>(&lo),
                              *reinterpret_cast<unsigned*>(&hi));
        *reinterpret_cast<uint2*>(&Xs[row * G2_LDA + c4]) = pk;
    }
    // C tile: 128 i-rows x 64 n bf16 (4 uint2/thread)
#pragma unroll
    for (int q = 0; q < 4; q++) {
        int idx = tid + 512 * q;
        int i   = idx >> 4;
        int k   = (idx & 15) << 2;
        uint2 pk = *reinterpret_cast<const uint2*>(&g_Cb[(size_t)(i0 + i) * NDIM + k]);
        *reinterpret_cast<uint2*>(&Cs[i * G2_LDA + k]) = pk;
    }
    __syncthreads();

    wmma::fragment<wmma::accumulator, 16, 16, 16, float> acc[2][2];
#pragma unroll
    for (int a = 0; a < 2; a++)
#pragma unroll
        for (int bb = 0; bb < 2; bb++) wmma::fill_fragment(acc[a][bb], 0.f);

#pragma unroll
    for (int ks = 0; ks < 4; ks++) {
        int k = ks * 16;
        wmma::fragment<wmma::matrix_a, 16, 16, 16, __nv_bfloat16, wmma::row_major> af[2];
        wmma::fragment<wmma::matrix_b, 16, 16, 16, __nv_bfloat16, wmma::col_major> bf[2];
#pragma unroll
        for (int mi = 0; mi < 2; mi++)
            wmma::load_matrix_sync(af[mi], &Xs[(wy * 32 + mi * 16) * G2_LDA + k], G2_LDA);
#pragma unroll
        for (int ni = 0; ni < 2; ni++)
            wmma::load_matrix_sync(bf[ni], &Cs[(wx * 32 + ni * 16) * G2_LDA + k], G2_LDA);
#pragma unroll
        for (int mi = 0; mi < 2; mi++)
#pragma unroll
            for (int ni = 0; ni < 2; ni++)
                wmma::mma_sync(acc[mi][ni], af[mi], bf[ni], acc[mi][ni]);
    }
    __syncthreads();   // Xs/Cs dead; Ys (64-row) aliases them

    // ---- half 0: rows 0..63 ----
    if (wy < 2) {
#pragma unroll
        for (int mi = 0; mi < 2; mi++)
#pragma unroll
            for (int ni = 0; ni < 2; ni++)
                wmma::store_matrix_sync(
                    &Ys[(wy * 32 + mi * 16) * G2_LDY + wx * 32 + ni * 16],
                    acc[mi][ni], G2_LDY, wmma::mem_row_major);
    }
    asm volatile("cp.async.wait_group 0;");
    __syncthreads();

#pragma unroll
    for (int q = 0; q < 4; q++) {
        int idx = tid + 512 * q;
        int row = idx >> 5;                      // 0..63
        int col = (idx & 31) << 2;
        int grow = m0 + row;
        float4 uv = *reinterpret_cast<const float4*>(&Us[row * 128 + col]);
        float4 dv = *reinterpret_cast<const float4*>(&D[i0 + col]);
        float4 sv = *reinterpret_cast<const float4*>(&Ys[row * G2_LDY + col]);
        float4 o;
        o.x = sv.x + dv.x * uv.x;
        o.y = sv.y + dv.y * uv.y;
        o.z = sv.z + dv.z * uv.z;
        o.w = sv.w + dv.w * uv.w;
        *reinterpret_cast<float4*>(&y[(size_t)grow * IDIM + i0 + col]) = o;
    }
    __syncthreads();   // half-0 Ys reads done

    // ---- half 1: rows 64..127 ----
    if (wy >= 2) {
#pragma unroll
        for (int mi = 0; mi < 2; mi++)
#pragma unroll
            for (int ni = 0; ni < 2; ni++)
                wmma::store_matrix_sync(
                    &Ys[(wy * 32 + mi * 16 - 64) * G2_LDY + wx * 32 + ni * 16],
                    acc[mi][ni], G2_LDY, wmma::mem_row_major);
    }
    __syncthreads();

#pragma unroll
    for (int q = 0; q < 4; q++) {
        int idx = tid + 512 * q;
        int row = idx >> 5;                      // 0..63
        int col = (idx & 31) << 2;
        int grow = m0 + 64 + row;
        float4 uv = *reinterpret_cast<const float4*>(&Us[(row + 64) * 128 + col]);
        float4 dv = *reinterpret_cast<const float4*>(&D[i0 + col]);
        float4 sv = *reinterpret_cast<const float4*>(&Ys[row * G2_LDY + col]);
        float4 o;
        o.x = sv.x + dv.x * uv.x;
        o.y = sv.y + dv.y * uv.y;
        o.z = sv.z + dv.z * uv.z;
        o.w = sv.w + dv.w * uv.w;
        *reinterpret_cast<float4*>(&y[(size_t)grow * IDIM + i0 + col]) = o;
    }
}

// ---------------------------------------------------------------------------
extern "C" void kernel_launch(void* const* d_in, const int* in_sizes, int n_in,
                              void* d_out, int out_size) {
    const float* u        = (const float*)d_in[0];
    const float* logA     = (const float*)d_in[1];
    const float* B        = (const float*)d_in[2];
    const float* C        = (const float*)d_in[3];
    const float* D        = (const float*)d_in[4];
    const float* logdelta = (const float*)d_in[5];
    float* y = (float*)d_out;

    cudaFuncSetAttribute(k_gemm1, cudaFuncAttributeMaxDynamicSharedMemorySize, G1_SMEM);
    cudaFuncSetAttribute(k_gemm2, cudaFuncAttributeMaxDynamicSharedMemorySize, G2_SMEM);

    k_setup<<<NDIM, 256>>>(logA, B, logdelta);
    k_gemm1<<<BT / 64 + 64, 256, G1_SMEM>>>(u, C);
    k_carry<<<BATCH + 1, NDIM>>>();
    dim3 g2(BT / 128, IDIM / 128);
    k_gemm2<<<g2, 512, G2_SMEM>>>(u, D, y);
}

// round 16
// speedup vs baseline: 1.0597x; 1.0597x over previous
#include <cuda_runtime.h>
#include <cuda_bf16.h>
#include <mma.h>
#include <cstdint>

using namespace nvcuda;

// Problem dims (fixed)
#define BATCH 8
#define TLEN  4096
#define IDIM  1024
#define NDIM  64
#define BT    (BATCH * TLEN)      // 32768
#define CH    64                  // scan chunk length (= K1 M tile)
#define NCH   (TLEN / CH)         // 64 chunks per batch

// ---------------------------------------------------------------------------
// Scratch (device globals; allocation forbidden)
// ---------------------------------------------------------------------------
__device__ __nv_bfloat16 g_Cb[IDIM * NDIM];      // C bf16 [i][n]
__device__ float g_a[NDIM];                      // A_bar_state
__device__ float g_Bu[(size_t)BT * NDIM];        // locally-scanned x (8 MB)
__device__ float g_end[BATCH * NCH * NDIM];      // chunk-local end states
__device__ float g_carry[BATCH * NCH * NDIM];    // carry-in per chunk
__device__ float g_apow[CH * NDIM];              // a_n^(t+1), t=0..63

// ---------------------------------------------------------------------------
// K0 (slim): a_n = mean_i exp(softplus(logdelta_i) * A_n).  One block per n.
// ---------------------------------------------------------------------------
__global__ void k_setup(const float* __restrict__ logA,
                        const float* __restrict__ logdelta) {
    int n = blockIdx.x;
    float A = -expf(logA[n]);
    __shared__ float red[256];
    float s = 0.f;
    for (int i = threadIdx.x; i < IDIM; i += 256) {
        float ld = logdelta[i];
        float d  = (ld > 20.f) ? ld : log1pf(expf(ld));
        s += expf(d * A);
    }
    red[threadIdx.x] = s;
    __syncthreads();
    for (int o = 128; o > 0; o >>= 1) {
        if (threadIdx.x < o) red[threadIdx.x] += red[threadIdx.x + o];
        __syncthreads();
    }
    if (threadIdx.x == 0) g_a[n] = red[0] * (1.f / IDIM);
}

// ---------------------------------------------------------------------------
// K1: wmma GEMM1 + in-smem local scan epilogue (R13 ping-pong), with Bbar
//     computed ON THE FLY: B fp32 * delta (smem table) -> bf16 at staging.
//     Trailing 64 blocks convert C -> bf16.
// ---------------------------------------------------------------------------
#define G1_LDA 72
#define G1_LDY 68
#define G1_AS   0                                 // 2 x 9216
#define G1_BS   (2 * 64 * G1_LDA * 2)             // 18432, 2 x 9216
#define G1_STG  (64 * G1_LDA * 2)                 // stage stride 9216
#define G1_YBU  0
#define G1_SEG  (64 * G1_LDY * 4)                 // 17408
#define G1_DL   36864                             // delta table, 4096 B
#define G1_SMEM (G1_DL + 4096)                    // 40960

__global__ __launch_bounds__(256) void k_gemm1(const float* __restrict__ u,
                                               const float* __restrict__ B,
                                               const float* __restrict__ C,
                                               const float* __restrict__ logdelta) {
    if (blockIdx.x >= BT / 64) {                  // C-convert blocks
        int idx = (blockIdx.x - BT / 64) * 256 + threadIdx.x;
        float4 v = *reinterpret_cast<const float4*>(C + 4 * (size_t)idx);
        __nv_bfloat162 lo = __floats2bfloat162_rn(v.x, v.y);
        __nv_bfloat162 hi = __floats2bfloat162_rn(v.z, v.w);
        uint2 pk = make_uint2(*reinterpret_cast<unsigned*>(&lo),
                              *reinterpret_cast<unsigned*>(&hi));
        *reinterpret_cast<uint2*>(&g_Cb[4 * (size_t)idx]) = pk;
        return;
    }
    extern __shared__ char smem[];
    float*        Ybu = reinterpret_cast<float*>(smem + G1_YBU);
    float*        seg = reinterpret_cast<float*>(smem + G1_SEG);
    float*        dl  = reinterpret_cast<float*>(smem + G1_DL);

    const int tid = threadIdx.x;
    const int wid = tid >> 5;
    const int wy  = wid >> 2;                    // 0..1 -> m offset 32*wy
    const int wx  = wid & 3;                     // 0..3 -> n offset 16*wx
    const int m0  = blockIdx.x * 64;
    const float* ub = &u[(size_t)m0 * IDIM];

    // delta table (1024 softplus), once per block
#pragma unroll
    for (int q = 0; q < 4; q++) {
        int i = tid + 256 * q;
        float ld = logdelta[i];
        dl[i] = (ld > 20.f) ? ld : log1pf(expf(ld));
    }

    wmma::fragment<wmma::accumulator, 16, 16, 16, float> acc[2];
#pragma unroll
    for (int a = 0; a < 2; a++) wmma::fill_fragment(acc[a], 0.f);

    // prefetch chunk 0: u and raw B (fp32)
    float4 r[4], rB[4];
#pragma unroll
    for (int q = 0; q < 4; q++) {
        int idx = tid + 256 * q;
        int row = idx >> 4;
        int k   = (idx & 15) << 2;
        r[q]  = *reinterpret_cast<const float4*>(&ub[(size_t)row * IDIM + k]);
        rB[q] = *reinterpret_cast<const float4*>(&B[(size_t)row * IDIM + k]);
    }
    __syncthreads();   // dl ready

    int buf = 0;
    for (int kc = 0; kc < IDIM; kc += 64) {
        __nv_bfloat16* As = reinterpret_cast<__nv_bfloat16*>(smem + G1_AS + buf * G1_STG);
        __nv_bfloat16* Bs = reinterpret_cast<__nv_bfloat16*>(smem + G1_BS + buf * G1_STG);
#pragma unroll
        for (int q = 0; q < 4; q++) {
            int idx = tid + 256 * q;
            int row = idx >> 4;
            int k   = (idx & 15) << 2;
            // u -> bf16
            __nv_bfloat162 lo = __floats2bfloat162_rn(r[q].x, r[q].y);
            __nv_bfloat162 hi = __floats2bfloat162_rn(r[q].z, r[q].w);
            uint2 pk = make_uint2(*reinterpret_cast<unsigned*>(&lo),
                                  *reinterpret_cast<unsigned*>(&hi));
            *reinterpret_cast<uint2*>(&As[row * G1_LDA + k]) = pk;
            // Bbar = B * delta -> bf16
            float4 dv = *reinterpret_cast<const float4*>(&dl[kc + k]);
            __nv_bfloat162 bl = __floats2bfloat162_rn(rB[q].x * dv.x, rB[q].y * dv.y);
            __nv_bfloat162 bh = __floats2bfloat162_rn(rB[q].z * dv.z, rB[q].w * dv.w);
            uint2 bk = make_uint2(*reinterpret_cast<unsigned*>(&bl),
                                  *reinterpret_cast<unsigned*>(&bh));
            *reinterpret_cast<uint2*>(&Bs[row * G1_LDA + k]) = bk;
        }
        __syncthreads();

        if (kc + 64 < IDIM) {
#pragma unroll
            for (int q = 0; q < 4; q++) {
                int idx = tid + 256 * q;
                int row = idx >> 4;
                int k   = (idx & 15) << 2;
                r[q]  = *reinterpret_cast<const float4*>(
                    &ub[(size_t)row * IDIM + kc + 64 + k]);
                rB[q] = *reinterpret_cast<const float4*>(
                    &B[(size_t)row * IDIM + kc + 64 + k]);
            }
        }

#pragma unroll
        for (int ks = 0; ks < 4; ks++) {
            int k = ks * 16;
            wmma::fragment<wmma::matrix_a, 16, 16, 16, __nv_bfloat16, wmma::row_major> af[2];
            wmma::fragment<wmma::matrix_b, 16, 16, 16, __nv_bfloat16, wmma::col_major> bf;
#pragma unroll
            for (int mi = 0; mi < 2; mi++)
                wmma::load_matrix_sync(af[mi], &As[(wy * 32 + mi * 16) * G1_LDA + k], G1_LDA);
            wmma::load_matrix_sync(bf, &Bs[(wx * 16) * G1_LDA + k], G1_LDA);
#pragma unroll
            for (int mi = 0; mi < 2; mi++)
                wmma::mma_sync(acc[mi], af[mi], bf, acc[mi]);
        }
        buf ^= 1;
    }
    __syncthreads();

#pragma unroll
    for (int mi = 0; mi < 2; mi++)
        wmma::store_matrix_sync(&Ybu[(wy * 32 + mi * 16) * G1_LDY + wx * 16],
                                acc[mi], G1_LDY, wmma::mem_row_major);
    __syncthreads();

    const int n = tid & 63, q = tid >> 6;
    const float a = g_a[n];
    {
        float* p = &Ybu[(q * 16) * G1_LDY + n];
        float x = 0.f;
#pragma unroll
        for (int j = 0; j < 16; j++) {
            x = x * a + p[j * G1_LDY];
            p[j * G1_LDY] = x;
        }
        seg[q * 64 + n] = x;
    }
    __syncthreads();
    if (q > 0) {
        float a16 = a;
#pragma unroll
        for (int s = 0; s < 4; s++) a16 *= a16;   // a^16
        float S = seg[n];
        for (int pp = 1; pp < q; pp++) S = S * a16 + seg[pp * 64 + n];
        float f = S;
        float* p = &Ybu[(q * 16) * G1_LDY + n];
#pragma unroll
        for (int j = 0; j < 16; j++) {
            f *= a;
            p[j * G1_LDY] += f;
        }
    }
    __syncthreads();

#pragma unroll
    for (int qq = 0; qq < 4; qq++) {
        int idx = tid + 256 * qq;
        int row = idx >> 4;
        int c4  = (idx & 15) << 2;
        float4 v = *reinterpret_cast<const float4*>(&Ybu[row * G1_LDY + c4]);
        *reinterpret_cast<float4*>(&g_Bu[(size_t)(m0 + row) * NDIM + c4]) = v;
    }
    if (tid < 64) g_end[blockIdx.x * 64 + tid] = Ybu[63 * G1_LDY + tid];
}

// ---------------------------------------------------------------------------
// Kc: blocks 0..7 -> per-batch carry scan over 64 chunks; block 8 -> apow.
// ---------------------------------------------------------------------------
__global__ void k_carry() {
    int n = threadIdx.x;
    if (blockIdx.x < BATCH) {
        int b = blockIdx.x;
        float e[NCH];
#pragma unroll
        for (int c = 0; c < NCH; c++) e[c] = g_end[(b * NCH + c) * 64 + n];
        float a = g_a[n], aL = a;
#pragma unroll
        for (int s = 0; s < 6; s++) aL *= aL;     // a^64 = a^CH
        float carry = 0.f;
#pragma unroll
        for (int c = 0; c < NCH; c++) {
            g_carry[(b * NCH + c) * 64 + n] = carry;
            carry = carry * aL + e[c];
        }
    } else {
        float a = g_a[n], p = a;
        for (int j = 0; j < CH; j++) {
            g_apow[j * 64 + n] = p;               // a^(j+1)
            p *= a;
        }
    }
}

// ---------------------------------------------------------------------------
// K2: wmma GEMM2 (512 thr, 16 warps 4x4, warp tile 32x32) — R13/R10 config.
//   xs[t][n] = x_local + carry[chunk(t)][n]*apow[t%64][n]
//   y[m,i]   = sum_n C[i,n]*xs[m,n] + D[i]*u[m,i]
// smem: Xs(18432) + Cs(18432) bf16, aliased by Ys(67584 fp32) post-MMA.
// ---------------------------------------------------------------------------
#define G2_LDA 72
#define G2_LDY 132
#define G2_XS   0
#define G2_CS   18432
#define G2_YS   0
#define G2_SMEM (128 * G2_LDY * 4)               // 67584

__global__ __launch_bounds__(512, 2) void k_gemm2(const float* __restrict__ u,
                                                  const float* __restrict__ D,
                                                  float* __restrict__ y) {
    extern __shared__ char smem[];
    __nv_bfloat16* Xs = reinterpret_cast<__nv_bfloat16*>(smem + G2_XS);
    __nv_bfloat16* Cs = reinterpret_cast<__nv_bfloat16*>(smem + G2_CS);
    float*         Ys = reinterpret_cast<float*>(smem + G2_YS);

    const int tid = threadIdx.x;
    const int wid = tid >> 5;
    const int wy  = wid >> 2;                    // m offset 32*wy
    const int wx  = wid & 3;                     // i offset 32*wx
    const int m0  = blockIdx.x * 128;
    const int i0  = blockIdx.y * 128;
    const int chk2 = blockIdx.x * 2;             // first 64-chunk id in tile

    // xs tile: fixup + bf16 convert (4 float4/thread)
#pragma unroll
    for (int q = 0; q < 4; q++) {
        int idx = tid + 512 * q;
        int row = idx >> 4;                      // 0..127
        int c4  = (idx & 15) << 2;
        float4 bu = *reinterpret_cast<const float4*>(
            &g_Bu[(size_t)(m0 + row) * NDIM + c4]);
        float4 ap = *reinterpret_cast<const float4*>(&g_apow[(row & 63) * 64 + c4]);
        float4 cr = *reinterpret_cast<const float4*>(
            &g_carry[(chk2 + (row >> 6)) * 64 + c4]);
        float x0 = bu.x + cr.x * ap.x;
        float x1 = bu.y + cr.y * ap.y;
        float x2 = bu.z + cr.z * ap.z;
        float x3 = bu.w + cr.w * ap.w;
        __nv_bfloat162 lo = __floats2bfloat162_rn(x0, x1);
        __nv_bfloat162 hi = __floats2bfloat162_rn(x2, x3);
        uint2 pk = make_uint2(*reinterpret_cast<unsigned*>(&lo),
                              *reinterpret_cast<unsigned*>(&hi));
        *reinterpret_cast<uint2*>(&Xs[row * G2_LDA + c4]) = pk;
    }
    // C tile: 128 i-rows x 64 n bf16 (4 uint2/thread)
#pragma unroll
    for (int q = 0; q < 4; q++) {
        int idx = tid + 512 * q;
        int i   = idx >> 4;
        int k   = (idx & 15) << 2;
        uint2 pk = *reinterpret_cast<const uint2*>(&g_Cb[(size_t)(i0 + i) * NDIM + k]);
        *reinterpret_cast<uint2*>(&Cs[i * G2_LDA + k]) = pk;
    }
    __syncthreads();

    wmma::fragment<wmma::accumulator, 16, 16, 16, float> acc[2][2];
#pragma unroll
    for (int a = 0; a < 2; a++)
#pragma unroll
        for (int bb = 0; bb < 2; bb++) wmma::fill_fragment(acc[a][bb], 0.f);

#pragma unroll
    for (int ks = 0; ks < 4; ks++) {
        int k = ks * 16;
        wmma::fragment<wmma::matrix_a, 16, 16, 16, __nv_bfloat16, wmma::row_major> af[2];
        wmma::fragment<wmma::matrix_b, 16, 16, 16, __nv_bfloat16, wmma::col_major> bf[2];
#pragma unroll
        for (int mi = 0; mi < 2; mi++)
            wmma::load_matrix_sync(af[mi], &Xs[(wy * 32 + mi * 16) * G2_LDA + k], G2_LDA);
#pragma unroll
        for (int ni = 0; ni < 2; ni++)
            wmma::load_matrix_sync(bf[ni], &Cs[(wx * 32 + ni * 16) * G2_LDA + k], G2_LDA);
#pragma unroll
        for (int mi = 0; mi < 2; mi++)
#pragma unroll
            for (int ni = 0; ni < 2; ni++)
                wmma::mma_sync(acc[mi][ni], af[mi], bf[ni], acc[mi][ni]);
    }
    __syncthreads();   // Xs/Cs dead; Ys aliases them

#pragma unroll
    for (int mi = 0; mi < 2; mi++)
#pragma unroll
        for (int ni = 0; ni < 2; ni++)
            wmma::store_matrix_sync(&Ys[(wy * 32 + mi * 16) * G2_LDY + wx * 32 + ni * 16],
                                    acc[mi][ni], G2_LDY, wmma::mem_row_major);
    __syncthreads();

    // epilogue: y = Ys + D*u  (8 float4/thread)
#pragma unroll 2
    for (int q = 0; q < 8; q++) {
        int idx = tid + 512 * q;
        int row = idx >> 5;
        int col = (idx & 31) << 2;
        int grow = m0 + row;
        int gcol = i0 + col;
        float4 uv = *reinterpret_cast<const float4*>(&u[(size_t)grow * IDIM + gcol]);
        float4 dv = *reinterpret_cast<const float4*>(&D[gcol]);
        float4 sv = *reinterpret_cast<const float4*>(&Ys[row * G2_LDY + col]);
        float4 o;
        o.x = sv.x + dv.x * uv.x;
        o.y = sv.y + dv.y * uv.y;
        o.z = sv.z + dv.z * uv.z;
        o.w = sv.w + dv.w * uv.w;
        *reinterpret_cast<float4*>(&y[(size_t)grow * IDIM + gcol]) = o;
    }
}

// ---------------------------------------------------------------------------
extern "C" void kernel_launch(void* const* d_in, const int* in_sizes, int n_in,
                              void* d_out, int out_size) {
    const float* u        = (const float*)d_in[0];
    const float* logA     = (const float*)d_in[1];
    const float* B        = (const float*)d_in[2];
    const float* C        = (const float*)d_in[3];
    const float* D        = (const float*)d_in[4];
    const float* logdelta = (const float*)d_in[5];
    float* y = (float*)d_out;

    cudaFuncSetAttribute(k_gemm1, cudaFuncAttributeMaxDynamicSharedMemorySize, G1_SMEM);
    cudaFuncSetAttribute(k_gemm2, cudaFuncAttributeMaxDynamicSharedMemorySize, G2_SMEM);

    k_setup<<<NDIM, 256>>>(logA, logdelta);
    k_gemm1<<<BT / 64 + 64, 256, G1_SMEM>>>(u, B, C, logdelta);
    k_carry<<<BATCH + 1, NDIM>>>();
    dim3 g2(BT / 128, IDIM / 128);
    k_gemm2<<<g2, 512, G2_SMEM>>>(u, D, y);
}